// round 2
// baseline (speedup 1.0000x reference)
#include <cuda_runtime.h>

#define NN      30000
#define DD      32
#define HH      128
#define KD      10
#define TILE_M  128
#define THREADS 512
#define AP      144                   // A row pitch in floats (>=141, %4==0)
#define SMEM_BYTES (TILE_M * AP * 4)  // 73728 B -> 2 CTAs/SM

typedef unsigned long long ull;

__device__ __forceinline__ ull pack2(float a, float b) {
    ull r; asm("mov.b64 %0, {%1, %2};" : "=l"(r) : "f"(a), "f"(b)); return r;
}
__device__ __forceinline__ ull fma2(ull a, ull b, ull c) {
    ull d; asm("fma.rn.f32x2 %0, %1, %2, %3;" : "=l"(d) : "l"(a), "l"(b), "l"(c)); return d;
}
__device__ __forceinline__ float2 unpk(ull v) {
    float2 r; asm("mov.b64 {%0, %1}, %2;" : "=f"(r.x), "=f"(r.y) : "l"(v)); return r;
}

__device__ float g_c[HH];     // relu(Wt4) @ Wt3
__device__ float g_bsum[HH];  // b0 + b1 + b2

__global__ void prep_kernel(const float* __restrict__ Wt3,
                            const float* __restrict__ Wt4,
                            const float* __restrict__ b0,
                            const float* __restrict__ b1,
                            const float* __restrict__ b2) {
    int j = threadIdx.x;
    float acc = 0.f;
#pragma unroll 8
    for (int h = 0; h < HH; ++h) {
        float r = Wt4[h];
        r = r > 0.f ? r : 0.f;
        acc += r * Wt3[h * HH + j];
    }
    g_c[j] = acc;
    g_bsum[j] = b0[j] + b1[j] + b2[j];
}

// One GEMM k-step: B row from global (lane-coalesced float4), A scalar broadcast from smem.
__device__ __forceinline__ void gstep(const float* __restrict__ brow,
                                      const float* __restrict__ As,
                                      int ka, int lane, int mb, ull acc[8][2]) {
    union { float4 f; ull v[2]; } b;
    b.f = __ldg((const float4*)brow + lane);
#pragma unroll
    for (int i = 0; i < 8; ++i) {
        float a = As[(mb + i) * AP + ka];
        ull a2 = pack2(a, a);
        acc[i][0] = fma2(a2, b.v[0], acc[i][0]);
        acc[i][1] = fma2(a2, b.v[1], acc[i][1]);
    }
}

__global__ void __launch_bounds__(THREADS, 2)
gcn_kernel(const float* __restrict__ feature, const float* __restrict__ x,
           const float* __restrict__ label,   const float* __restrict__ w,
           const float* __restrict__ et,      const int*   __restrict__ src,
           const float* __restrict__ W0,      const float* __restrict__ W1,
           const float* __restrict__ W2,      float* __restrict__ out) {
    extern __shared__ float As[];   // [TILE_M][AP]: k rows 0..127 n1_h, 128..129 x,
                                    // 130..139 label, 140 S
    const int tid  = threadIdx.x;
    const int warp = tid >> 5, lane = tid & 31;
    const int n0   = blockIdx.x * TILE_M;
    const float4* feat4 = (const float4*)feature;

    // ---------- phase 1: one warp per node (8 nodes/warp), meta in regs + shfl
    for (int m = warp; m < TILE_M; m += 16) {
        int n  = n0 + m;
        int nn = n < NN ? n : 0;                 // clamp: garbage rows never stored
        int   s_l = src[nn * DD + lane];         // coalesced
        float e_l = et[(nn * DD + lane) * 2];    // stride-2
        float S   = w[nn * DD + lane] * e_l;
#pragma unroll
        for (int o = 16; o; o >>= 1) S += __shfl_xor_sync(0xffffffffu, S, o);

        ull a0 = 0, a1 = 0;
#pragma unroll
        for (int d = 0; d < DD; ++d) {
            int   s = __shfl_sync(0xffffffffu, s_l, d);
            float e = __shfl_sync(0xffffffffu, e_l, d);
            union { float4 f; ull v[2]; } u;
            u.f = __ldg(feat4 + s * (HH / 4) + lane);   // 512B coalesced row slice
            ull e2 = pack2(e, e);
            a0 = fma2(u.v[0], e2, a0);
            a1 = fma2(u.v[1], e2, a1);
        }
        float2 p0 = unpk(a0), p1 = unpk(a1);
        float4 st; st.x = p0.x; st.y = p0.y; st.z = p1.x; st.w = p1.y;
        ((float4*)(As + m * AP))[lane] = st;
        if (lane == 0) As[m * AP + 140] = S;
        if (lane < 2)  As[m * AP + 128 + lane] = x[nn * 2 + lane];
        if (lane < KD) As[m * AP + 130 + lane] = label[nn * KD + lane];
    }
    __syncthreads();

    // ---------- phase 2: out[128][128] = relu(A[128][141] @ B[141][128] + bsum)
    const int j0 = lane * 4;       // 4 output cols per thread
    const int mb = warp * 8;       // 8 output rows per thread
    ull acc[8][2];
    {
        union { float4 f; ull v[2]; } bi;
        bi.f = __ldg((const float4*)g_bsum + lane);
#pragma unroll
        for (int i = 0; i < 8; ++i) { acc[i][0] = bi.v[0]; acc[i][1] = bi.v[1]; }
    }

#pragma unroll 4
    for (int k = 0; k < HH; ++k) gstep(W2 + k * HH, As, k, lane, mb, acc);
    gstep(W0,       As, 128, lane, mb, acc);
    gstep(W0 + HH,  As, 129, lane, mb, acc);
#pragma unroll
    for (int k = 0; k < KD; ++k) gstep(W1 + k * HH, As, 130 + k, lane, mb, acc);
    gstep(g_c, As, 140, lane, mb, acc);

#pragma unroll
    for (int i = 0; i < 8; ++i) {
        int n = n0 + mb + i;
        if (n < NN) {
            float2 q0 = unpk(acc[i][0]), q1 = unpk(acc[i][1]);
            float4 r;
            r.x = fmaxf(q0.x, 0.f); r.y = fmaxf(q0.y, 0.f);
            r.z = fmaxf(q1.x, 0.f); r.w = fmaxf(q1.y, 0.f);
            *((float4*)(out + n * HH + j0)) = r;
        }
    }
}

extern "C" void kernel_launch(void* const* d_in, const int* in_sizes, int n_in,
                              void* d_out, int out_size) {
    const float* feature = (const float*)d_in[0];
    const float* x       = (const float*)d_in[1];
    const float* label   = (const float*)d_in[2];
    const float* w       = (const float*)d_in[3];
    const float* et      = (const float*)d_in[4];
    const int*   src     = (const int*)  d_in[5];
    const float* W0      = (const float*)d_in[6];
    const float* b0      = (const float*)d_in[7];
    const float* W1      = (const float*)d_in[8];
    const float* b1      = (const float*)d_in[9];
    const float* W2      = (const float*)d_in[10];
    const float* b2      = (const float*)d_in[11];
    const float* Wt3     = (const float*)d_in[12];
    const float* Wt4     = (const float*)d_in[13];
    float* out = (float*)d_out;

    cudaFuncSetAttribute(gcn_kernel, cudaFuncAttributeMaxDynamicSharedMemorySize,
                         SMEM_BYTES);

    prep_kernel<<<1, HH>>>(Wt3, Wt4, b0, b1, b2);
    gcn_kernel<<<(NN + TILE_M - 1) / TILE_M, THREADS, SMEM_BYTES>>>(
        feature, x, label, w, et, src, W0, W1, W2, out);
}